// round 3
// baseline (speedup 1.0000x reference)
#include <cuda_runtime.h>
#include <cuda_fp16.h>

#define R     8192
#define D     64
#define TW    1000
#define TTOT  2000
#define NB    128     // CTAs, 1 per SM
#define NT    1024    // 32 warps
#define WARPS 32
#define RPW   2       // rows per warp
#define RPC   64      // rows per CTA
#define PINR  11      // rows pinned in SMEM per CTA

// d_out layout (float32): prediction[1000,64], target[1000,64],
// prediction_augment[2000,64], target_augment[2000,64]
#define PRED_OFF 0
#define TGT_OFF  (1000*64)
#define PA_OFF   (2*1000*64)
#define TA_OFF   (4*1000*64)

static_assert(NB * RPC == R, "row partition");

// ---------------- device state ----------------
__device__ __half  d_Wh16[(size_t)R * R];   // 128 MB fp16 W_h (PERMUTED layout)
__device__ float   d_WoutT[(size_t)R * D];  // W_out transposed [r][i]
__device__ float   d_h[2][R];
__device__ float   d_osub[3][8][D];
__device__ unsigned d_bar_count;
__device__ unsigned d_bar_gen;

// ---------------- prologue: fp32 -> fp16, permuted for conflict-free LDS ----
// Output uint4 o for row r, block it, lane l holds src k = it*256 + l*4 + {0..3}
// in halves 0-3 and src k = it*256 + 128 + l*4 + {0..3} in halves 4-7.
__global__ void k_convert(const float* __restrict__ Wh) {
    size_t n = (size_t)R * R / 8;
    uint4* dst = (uint4*)d_Wh16;
    for (size_t o = (size_t)blockIdx.x * blockDim.x + threadIdx.x; o < n;
         o += (size_t)gridDim.x * blockDim.x) {
        size_t r = o >> 10;
        int rem = (int)(o & 1023);
        int it = rem >> 5, lane = rem & 31;
        const float* base = Wh + r * R + it * 256 + lane * 4;
        float4 a = *(const float4*)base;
        float4 b = *(const float4*)(base + 128);
        __half2 p0 = __floats2half2_rn(a.x, a.y);
        __half2 p1 = __floats2half2_rn(a.z, a.w);
        __half2 p2 = __floats2half2_rn(b.x, b.y);
        __half2 p3 = __floats2half2_rn(b.z, b.w);
        uint4 q;
        q.x = *reinterpret_cast<unsigned*>(&p0);
        q.y = *reinterpret_cast<unsigned*>(&p1);
        q.z = *reinterpret_cast<unsigned*>(&p2);
        q.w = *reinterpret_cast<unsigned*>(&p3);
        dst[o] = q;
    }
}

// ---------------- prologue: transpose W_out, copy targets, init ----------------
__global__ void k_prep(const float* __restrict__ Wout,
                       const float* __restrict__ xin,
                       float* __restrict__ out) {
    int tid = blockIdx.x * blockDim.x + threadIdx.x;
    int stride = gridDim.x * blockDim.x;
    for (int i = tid; i < R * D; i += stride) {
        int r = i / D, c = i % D;
        d_WoutT[i] = Wout[(size_t)c * R + r];
    }
    for (int i = tid; i < TTOT * D; i += stride) {
        float v = xin[i];
        out[TA_OFF + i] = v;
        if (i >= TW * D) out[TGT_OFF + i - TW * D] = v;
    }
    for (int i = tid; i < R; i += stride) { d_h[0][i] = 0.f; d_h[1][i] = 0.f; }
    if (tid < 3 * 8 * D) ((float*)d_osub)[tid] = 0.f;
    if (tid == 0) { d_bar_count = 0; d_bar_gen = 0; }
}

// ---------------- grid barrier ----------------
__device__ __forceinline__ void gridbar() {
    __threadfence();
    __syncthreads();
    if (threadIdx.x == 0) {
        volatile unsigned* vgen = (volatile unsigned*)&d_bar_gen;
        unsigned g = *vgen;
        unsigned a = atomicAdd(&d_bar_count, 1u);
        if (a == NB - 1) {
            *(volatile unsigned*)&d_bar_count = 0;
            __threadfence();
            *vgen = g + 1;
        } else {
            while (*vgen == g) { }
        }
        __threadfence();
    }
    __syncthreads();
}

// packed dual-FMA: acc += a * b (2 fp32 lanes)
__device__ __forceinline__ void ffma2(float2& acc, float2 a, float2 b) {
    asm("{\n\t"
        ".reg .b64 ra, rb, rc;\n\t"
        "mov.b64 ra, {%2, %3};\n\t"
        "mov.b64 rb, {%4, %5};\n\t"
        "mov.b64 rc, {%0, %1};\n\t"
        "fma.rn.f32x2 rc, ra, rb, rc;\n\t"
        "mov.b64 {%0, %1}, rc;\n\t"
        "}"
        : "+f"(acc.x), "+f"(acc.y)
        : "f"(a.x), "f"(a.y), "f"(b.x), "f"(b.y));
}

__device__ __forceinline__ void dot8acc(uint4 q, float4 ha, float4 hb, float2& acc) {
    const __half2* h2 = reinterpret_cast<const __half2*>(&q);
    float2 w0 = __half22float2(h2[0]);
    float2 w1 = __half22float2(h2[1]);
    float2 w2 = __half22float2(h2[2]);
    float2 w3 = __half22float2(h2[3]);
    ffma2(acc, w0, make_float2(ha.x, ha.y));
    ffma2(acc, w1, make_float2(ha.z, ha.w));
    ffma2(acc, w2, make_float2(hb.x, hb.y));
    ffma2(acc, w3, make_float2(hb.z, hb.w));
}

// dynamic smem layout
#define SM_WC    0                                // PINR*8192 halves = 180224 B
#define SM_H     (PINR * R * 2)                   // 8192 floats = 32768 B
#define SM_ORED  (SM_H + R * 4)                   // 32*64 floats = 8192 B
#define SM_X     (SM_ORED + WARPS * 64 * 4)       // 64 floats = 256 B
#define SM_TOTAL (SM_X + 64 * 4)                  // 221440 B

#define MM_BODY(SRC0, SRC1)                                        \
    _Pragma("unroll 2")                                            \
    for (int it = 0; it < 32; ++it) {                              \
        int kb = it * 256 + lane * 4;                              \
        float4 ha = *(const float4*)(h_sh + kb);                   \
        float4 hb = *(const float4*)(h_sh + kb + 128);             \
        uint4 q0 = SRC0[it * 32 + lane];                           \
        uint4 q1 = SRC1[it * 32 + lane];                           \
        dot8acc(q0, ha, hb, accA);                                 \
        dot8acc(q1, ha, hb, accB);                                 \
    }

// ---------------- persistent ESN kernel ----------------
__global__ void __launch_bounds__(NT, 1)
k_esn(const float* __restrict__ xin,
      const float* __restrict__ Win,
      float* __restrict__ out) {
    extern __shared__ char smem[];
    __half* wc   = (__half*)(smem + SM_WC);
    float*  h_sh = (float*)(smem + SM_H);
    float*  ored = (float*)(smem + SM_ORED);
    float*  x_sh = (float*)(smem + SM_X);

    const int tid  = threadIdx.x;
    const int lane = tid & 31;
    const int warp = tid >> 5;
    const int cta  = blockIdx.x;
    const int grow0 = cta * RPC + warp * RPW;

    // ---- pin first PINR rows of this CTA's slice in SMEM ----
    {
        const uint4* src = (const uint4*)(d_Wh16 + (size_t)cta * RPC * R);
        uint4* dst = (uint4*)wc;
        for (int i = tid; i < PINR * (R / 8); i += NT) dst[i] = src[i];
    }

    const uint4* g0 = (const uint4*)(d_Wh16 + (size_t)(grow0 + 0) * R);
    const uint4* g1 = (const uint4*)(d_Wh16 + (size_t)(grow0 + 1) * R);
    const uint4* c0 = (const uint4*)(wc + (size_t)(2 * warp + 0) * R);
    const uint4* c1 = (const uint4*)(wc + (size_t)(2 * warp + 1) * R);
    const float* winr = Win + (size_t)grow0 * D + 2 * lane;
    const float* wt   = d_WoutT + (size_t)grow0 * D;
    __syncthreads();

    for (int s = 0; s < TTOT; ++s) {
        // ---- publish out(h_s), prepare x, recycle buffers ----
        if (tid < D) {
            float o = 0.f;
            if (cta == 0 || s >= TW) {
                #pragma unroll
                for (int b = 0; b < 8; ++b) o += d_osub[s % 3][b][tid];
            }
            if (cta == 0) {
                if (s >= 1 && s <= TW) out[PA_OFF + (s - 1) * D + tid] = o;
                if (s >= TW) {
                    out[PRED_OFF + (s - TW) * D + tid] = o;
                    out[PA_OFF + s * D + tid] = o;
                }
            }
            if (cta < 8) d_osub[(s + 2) % 3][cta][tid] = 0.f;
            x_sh[tid] = (s < TW) ? xin[(size_t)s * D + tid] : o;
        }
        // ---- stage h_s into shared ----
        {
            const float4* hsrc = (const float4*)d_h[s & 1];
            for (int i = tid; i < R / 4; i += NT) ((float4*)h_sh)[i] = hsrc[i];
        }
        __syncthreads();

        // ---- W_h @ h : warps 0-4 SMEM, warp 5 mixed, warps 6-31 L2 ----
        float2 accA = make_float2(0.f, 0.f);
        float2 accB = make_float2(0.f, 0.f);
        if (warp < 5) {
            MM_BODY(c0, c1)
        } else if (warp == 5) {
            MM_BODY(c0, g1)     // row 10 pinned, row 11 from L2
        } else {
            MM_BODY(g0, g1)
        }

        // ---- + W_in @ x, horizontal pack-sum ----
        float xa = x_sh[2 * lane], xb = x_sh[2 * lane + 1];
        float a0 = accA.x + accA.y + winr[0] * xa + winr[1]     * xb;
        float a1 = accB.x + accB.y + winr[D] * xa + winr[D + 1] * xb;
        #pragma unroll
        for (int o = 16; o; o >>= 1) {
            a0 += __shfl_xor_sync(0xffffffffu, a0, o);
            a1 += __shfl_xor_sync(0xffffffffu, a1, o);
        }
        // ---- tanh, store h_{s+1}, aug broadcast ----
        float v0 = 0.f, v1 = 0.f;
        if (lane == 0) {
            float h0 = tanhf(a0), h1 = tanhf(a1);
            *(float2*)(d_h[(s + 1) & 1] + grow0) = make_float2(h0, h1);
            v0 = h0 * h0;   // even row -> squared
            v1 = h1;        // odd row  -> identity
        }
        v0 = __shfl_sync(0xffffffffu, v0, 0);
        v1 = __shfl_sync(0xffffffffu, v1, 0);

        // ---- fused readout partials ----
        float p0 = wt[lane]      * v0 + wt[D + lane]      * v1;
        float p1 = wt[32 + lane] * v0 + wt[D + 32 + lane] * v1;
        ored[warp * 64 + lane]      = p0;
        ored[warp * 64 + 32 + lane] = p1;
        __syncthreads();
        if (tid < D) {
            float sum = 0.f;
            #pragma unroll
            for (int w = 0; w < WARPS; ++w) sum += ored[w * 64 + tid];
            atomicAdd(&d_osub[(s + 1) % 3][cta & 7][tid], sum);
        }
        gridbar();
    }
}

// ---------------- launch ----------------
extern "C" void kernel_launch(void* const* d_in, const int* in_sizes, int n_in,
                              void* d_out, int out_size) {
    const float* xin  = (const float*)d_in[0];
    const float* Win  = (const float*)d_in[1];
    const float* Whf  = (const float*)d_in[2];
    const float* Wout = (const float*)d_in[3];
    float* out = (float*)d_out;

    static bool attr_set = false;
    if (!attr_set) {
        cudaFuncSetAttribute(k_esn, cudaFuncAttributeMaxDynamicSharedMemorySize, SM_TOTAL);
        attr_set = true;
    }

    k_convert<<<4096, 256>>>(Whf);
    k_prep<<<1024, 256>>>(Wout, xin, out);
    k_esn<<<NB, NT, SM_TOTAL>>>(xin, Win, out);
}